// round 7
// baseline (speedup 1.0000x reference)
#include <cuda_runtime.h>
#include <cuda_bf16.h>
#include <math.h>
#include <stdint.h>

#define BOX_P 32
#define PATCH_ELEMS (BOX_P * BOX_P)   // 1024
#define WARPS_PER_PATCH 4
#define ROWS_PER_WARP (BOX_P / WARPS_PER_PATCH)   // 8
#define WARPS_PER_CTA 8
#define PATCHES_PER_CTA (WARPS_PER_CTA / WARPS_PER_PATCH)  // 2
#define THREADS (WARPS_PER_CTA * 32)
#define EPSF 1e-6f

#define NBINS 4096          // 64 x 64 spatial tiles (64px granularity)
#define MAX_CORR 32768

__device__ int g_bin_cnt[NBINS];
__device__ int g_bin_off[NBINS];
__device__ int g_perm[MAX_CORR];

// ---- K0: zero counters + output ----
__global__ void lp_zero_kernel(float* out) {
    const int i = blockIdx.x * blockDim.x + threadIdx.x;
    if (i < NBINS) g_bin_cnt[i] = 0;
    if (i == 0) out[0] = 0.0f;
}

__device__ __forceinline__ int patch_key(int x, int y) {
    return (((x >> 6) & 63) << 6) | ((y >> 6) & 63);
}

// ---- K1: histogram by spatial tile ----
__global__ void lp_hist_kernel(const int* __restrict__ x0,
                               const int* __restrict__ y0, int n_corr) {
    const int i = blockIdx.x * blockDim.x + threadIdx.x;
    if (i < n_corr) atomicAdd(&g_bin_cnt[patch_key(x0[i], y0[i])], 1);
}

// ---- K2: exclusive prefix sum over 4096 bins (single CTA, 1024 threads) ----
__global__ __launch_bounds__(1024)
void lp_scan_kernel() {
    __shared__ int sh[1024];
    const int t = threadIdx.x;
    int local[4];
    int tsum = 0;
    #pragma unroll
    for (int j = 0; j < 4; j++) {
        local[j] = g_bin_cnt[t * 4 + j];
        tsum += local[j];
    }
    sh[t] = tsum;
    __syncthreads();
    // Hillis-Steele inclusive scan over thread sums
    #pragma unroll
    for (int off = 1; off < 1024; off <<= 1) {
        int v = (t >= off) ? sh[t - off] : 0;
        __syncthreads();
        sh[t] += v;
        __syncthreads();
    }
    int run = sh[t] - tsum;   // exclusive prefix for this thread's first bin
    #pragma unroll
    for (int j = 0; j < 4; j++) {
        g_bin_off[t * 4 + j] = run;
        run += local[j];
    }
}

// ---- K3: scatter patch ids into spatially sorted order ----
__global__ void lp_scatter_kernel(const int* __restrict__ x0,
                                  const int* __restrict__ y0, int n_corr) {
    const int i = blockIdx.x * blockDim.x + threadIdx.x;
    if (i < n_corr) {
        const int pos = atomicAdd(&g_bin_off[patch_key(x0[i], y0[i])], 1);
        g_perm[pos] = i;
    }
}

// ---- K4: main Pearson kernel (R5 structure + perm indirection) ----
__global__ __launch_bounds__(THREADS)
void lp_pearson_sorted_kernel(const float* __restrict__ pred,
                              const float* __restrict__ gt,
                              const int*   __restrict__ x0,
                              const int*   __restrict__ y0,
                              float* __restrict__ out,
                              int n_corr, int W)
{
    const int warp    = threadIdx.x >> 5;
    const int lane    = threadIdx.x & 31;
    const int plocal  = warp >> 2;          // 0..1: which patch slot in CTA
    const int quarter = warp & 3;           // 0..3: which 8-row slab
    const int slot = blockIdx.x * PATCHES_PER_CTA + plocal;
    const bool valid = (slot < n_corr);
    const int b = valid ? g_perm[slot] : 0;

    __shared__ float sh[WARPS_PER_CTA][5];

    float sp = 0.f, sg = 0.f, spp = 0.f, sgg = 0.f, spg = 0.f;

    if (valid) {
        const int X = x0[b] + quarter * ROWS_PER_WARP;
        const int Y = y0[b];
        const float* __restrict__ pbase = pred + (size_t)X * W + Y + lane;
        const float* __restrict__ gbase = gt   + (size_t)X * W + Y + lane;

        float p[ROWS_PER_WARP], g[ROWS_PER_WARP];
        #pragma unroll
        for (int r = 0; r < ROWS_PER_WARP; r++) {
            const size_t off = (size_t)r * W;
            p[r] = __ldg(pbase + off);
            g[r] = __ldg(gbase + off);
        }
        #pragma unroll
        for (int r = 0; r < ROWS_PER_WARP; r++) {
            sp  += p[r];
            sg  += g[r];
            spp += p[r] * p[r];
            sgg += g[r] * g[r];
            spg += p[r] * g[r];
        }
    }

    #pragma unroll
    for (int o = 16; o > 0; o >>= 1) {
        sp  += __shfl_down_sync(0xFFFFFFFFu, sp,  o);
        sg  += __shfl_down_sync(0xFFFFFFFFu, sg,  o);
        spp += __shfl_down_sync(0xFFFFFFFFu, spp, o);
        sgg += __shfl_down_sync(0xFFFFFFFFu, sgg, o);
        spg += __shfl_down_sync(0xFFFFFFFFu, spg, o);
    }

    if (lane == 0) {
        sh[warp][0] = sp;  sh[warp][1] = sg;  sh[warp][2] = spp;
        sh[warp][3] = sgg; sh[warp][4] = spg;
    }
    __syncthreads();

    if (quarter == 0 && lane == 0 && valid) {
        const int base = plocal * WARPS_PER_PATCH;
        float Sp = 0.f, Sg = 0.f, Spp = 0.f, Sgg = 0.f, Spg = 0.f;
        #pragma unroll
        for (int w = 0; w < WARPS_PER_PATCH; w++) {
            Sp  += sh[base + w][0];
            Sg  += sh[base + w][1];
            Spp += sh[base + w][2];
            Sgg += sh[base + w][3];
            Spg += sh[base + w][4];
        }

        const float P    = (float)PATCH_ELEMS;
        const float invP = 1.0f / P;
        const float mp = Sp * invP;
        const float mg = Sg * invP;
        // unbiased (ddof=1) variance, matching jnp.std(ddof=1)
        const float varp = (Spp - Sp * mp) / (P - 1.0f);
        const float varg = (Sgg - Sg * mg) / (P - 1.0f);
        const float sdp = sqrtf(fmaxf(varp, 0.f)) + EPSF;
        const float sdg = sqrtf(fmaxf(varg, 0.f)) + EPSF;
        const float cov = Spg - Sp * mg;   // = Spg - Sp*Sg/P
        const float co  = cov / (P * sdp * sdg);
        atomicAdd(out, (1.0f - co) / (float)n_corr);
    }
}

extern "C" void kernel_launch(void* const* d_in, const int* in_sizes, int n_in,
                              void* d_out, int out_size)
{
    const float* pred = (const float*)d_in[0];
    const float* gt   = (const float*)d_in[1];
    const int*   x0   = (const int*)d_in[2];
    const int*   y0   = (const int*)d_in[3];
    float* out = (float*)d_out;

    const int n_corr = in_sizes[2];

    // Derive W from the (square, C=1) image element count.
    int W = 1;
    while ((long long)W * W < (long long)in_sizes[0]) W <<= 1;

    const int nblk = (n_corr + 255) / 256;
    lp_zero_kernel<<<(NBINS + 255) / 256, 256>>>(out);
    lp_hist_kernel<<<nblk, 256>>>(x0, y0, n_corr);
    lp_scan_kernel<<<1, 1024>>>();
    lp_scatter_kernel<<<nblk, 256>>>(x0, y0, n_corr);

    const int grid = (n_corr + PATCHES_PER_CTA - 1) / PATCHES_PER_CTA;
    lp_pearson_sorted_kernel<<<grid, THREADS>>>(pred, gt, x0, y0, out, n_corr, W);
}